// round 6
// baseline (speedup 1.0000x reference)
#include <cuda_runtime.h>

#define B_  64
#define L_  200
#define NS_ 1000
#define D_  128
#define M_  50
#define BL_ (B_*L_)
#define WSTR 64   // padded w-row stride (slots 50..63 zero)

// -------- scratch (device globals; no allocation allowed) --------
__device__ float g_eWT[D_*D_];        // e_W transposed [k][d]
__device__ float g_aWT[D_*D_];        // a_W transposed
__device__ float g_frT[D_*D_];        // read-half of f_W transposed [k][d]
__device__ float g_fkT[D_*D_];        // k-half of f_W transposed
__device__ float g_wtab[1024*WSTR];   // softmax weights per skill (padded)
__device__ float g_etab[2016*D_];     // sigmoid erase per x
__device__ float g_atab[2016*D_];     // tanh add per x
__device__ float g_kftab[1024*D_];    // k_emb[s] @ f_Wk^T (no bias/act)
__device__ float g_read[BL_*D_];      // read vectors

__device__ __forceinline__ float fsigmoid(float x){ return 1.f/(1.f+__expf(-x)); }
__device__ __forceinline__ float ftanh(float x){ float y; asm("tanh.approx.f32 %0, %1;":"=f"(y):"f"(x)); return y; }

// =====================================================================
// Kernel 0: transpose the 4 weight matrices once (tiled, conflict-free).
// grid (16, 4): blockIdx.y = matrix, blockIdx.x = 32x32 tile. 256 thr.
// =====================================================================
extern "C" __global__ void __launch_bounds__(256)
k0_transpose(const float* __restrict__ e_W, const float* __restrict__ a_W,
             const float* __restrict__ f_W)
{
    __shared__ float tile[32][33];
    const int m  = blockIdx.y;
    const int tb = blockIdx.x;
    const int d0 = (tb & 3) * 32;       // src row block
    const int k0 = (tb >> 2) * 32;      // src col block
    const int c  = threadIdx.x & 31;
    const int rb = threadIdx.x >> 5;    // 8 rows per pass

    const float* src; int stride, off; float* dst;
    if      (m == 0) { src = e_W; stride = D_;   off = 0;   dst = g_eWT; }
    else if (m == 1) { src = a_W; stride = D_;   off = 0;   dst = g_aWT; }
    else if (m == 2) { src = f_W; stride = 2*D_; off = 0;   dst = g_frT; }
    else             { src = f_W; stride = 2*D_; off = D_;  dst = g_fkT; }

    #pragma unroll
    for (int p = 0; p < 4; p++) {
        int r = rb + p*8;
        tile[r][c] = src[(size_t)(d0 + r)*stride + off + k0 + c];
    }
    __syncthreads();
    #pragma unroll
    for (int p = 0; p < 4; p++) {
        int r = rb + p*8;
        dst[(size_t)(k0 + r)*D_ + d0 + c] = tile[c][r];
    }
}

// =====================================================================
// Kernel A: build all tables. 190 blocks x 256 threads, 80KB smem
//  -> 2 blocks/SM. Weight staging = straight float4 copy of transposed
//  gmem weights (coalesced, conflict-free). Block types:
//   [0,63)    e-table   [63,126) a-table
//   [126,158) w-table (softmax)   [158,190) kf-table
// =====================================================================
extern "C" __global__ void __launch_bounds__(256, 2)
kA_tables(const float* __restrict__ k_emb, const float* __restrict__ v_emb,
          const float* __restrict__ Mk,
          const float* __restrict__ e_b, const float* __restrict__ a_b)
{
    extern __shared__ float sm[];
    float* sx = sm;                 // 32*128 activation tile (16KB)
    float* sw = sm + 32*D_;         // 128*128 transposed weights (64KB)
    const int tid = threadIdx.x;
    const int tx = tid & 31, ty = tid >> 5;
    const int r0 = ty * 4, c0 = tx * 4;
    const int bid = blockIdx.x;

    if (bid < 126 || bid >= 158) {
        // ------- e-table / a-table / kf-table (dense 128x128 GEMM) -------
        const int type  = (bid < 63) ? 0 : (bid < 126) ? 1 : 2;
        const int rbase = (type == 0 ? bid : type == 1 ? bid - 63 : bid - 158) * 32;
        const float* WT = (type == 0) ? g_eWT : (type == 1) ? g_aWT : g_fkT;
        const float* xs = (type == 2) ? k_emb : v_emb;
        const int rmax  = (type == 2) ? NS_ - 1 : 2*NS_ - 1;

        {   // stage transposed weights: straight copy, conflict-free
            float4* sw4 = (float4*)sw;
            const float4* WT4 = (const float4*)WT;
            #pragma unroll
            for (int i = 0; i < 16; i++) sw4[tid + i*256] = __ldg(&WT4[tid + i*256]);
        }
        {   // gather 32 activation rows
            float4* s4 = (float4*)sx;
            const float4* xs4 = (const float4*)xs;
            for (int u = tid; u < 32*32; u += 256) {
                int r = u >> 5, cc = u & 31;
                int rr = min(rbase + r, rmax);
                s4[r*32 + cc] = __ldg(&xs4[(size_t)rr*32 + cc]);
            }
        }
        __syncthreads();

        float acc[4][4] = {};
        const float4* s4 = (const float4*)sx;
        #pragma unroll 4
        for (int k4 = 0; k4 < 32; k4++) {
            float4 vr[4];
            #pragma unroll
            for (int i = 0; i < 4; i++) vr[i] = s4[(r0+i)*32 + k4];
            #pragma unroll
            for (int s = 0; s < 4; s++) {
                int k = 4*k4 + s;
                float4 w = *(const float4*)&sw[k*D_ + c0];
                #pragma unroll
                for (int i = 0; i < 4; i++) {
                    float vv = ((const float*)&vr[i])[s];
                    acc[i][0] = fmaf(vv, w.x, acc[i][0]);
                    acc[i][1] = fmaf(vv, w.y, acc[i][1]);
                    acc[i][2] = fmaf(vv, w.z, acc[i][2]);
                    acc[i][3] = fmaf(vv, w.w, acc[i][3]);
                }
            }
        }
        #pragma unroll
        for (int i = 0; i < 4; i++) {
            int row = rbase + r0 + i;
            float4 o;
            if (type == 0) {
                float4 bb = *(const float4*)&e_b[c0];
                o.x = fsigmoid(acc[i][0] + bb.x); o.y = fsigmoid(acc[i][1] + bb.y);
                o.z = fsigmoid(acc[i][2] + bb.z); o.w = fsigmoid(acc[i][3] + bb.w);
                *(float4*)&g_etab[(size_t)row*D_ + c0] = o;
            } else if (type == 1) {
                float4 bb = *(const float4*)&a_b[c0];
                o.x = ftanh(acc[i][0] + bb.x); o.y = ftanh(acc[i][1] + bb.y);
                o.z = ftanh(acc[i][2] + bb.z); o.w = ftanh(acc[i][3] + bb.w);
                *(float4*)&g_atab[(size_t)row*D_ + c0] = o;
            } else {
                o.x = acc[i][0]; o.y = acc[i][1]; o.z = acc[i][2]; o.w = acc[i][3];
                *(float4*)&g_kftab[(size_t)row*D_ + c0] = o;
            }
        }
    } else {
        // ---------------- w (softmax) table ----------------
        const int rbase = (bid - 126) * 32;
        float* MkT = sw;                      // 128*65 (pad 65: conflict-free)
        for (int i = tid; i < M_*D_; i += 256) {
            int m = i >> 7, k = i & 127;
            MkT[k*65 + m] = Mk[i];
        }
        for (int i = tid; i < D_*14; i += 256) {
            int k = i / 14, m = 50 + (i % 14);
            MkT[k*65 + m] = 0.f;
        }
        {
            float4* s4 = (float4*)sx;
            const float4* ke4 = (const float4*)k_emb;
            for (int u = tid; u < 32*32; u += 256) {
                int r = u >> 5, cc = u & 31;
                int rr = min(rbase + r, NS_ - 1);
                s4[r*32 + cc] = __ldg(&ke4[(size_t)rr*32 + cc]);
            }
        }
        __syncthreads();

        const int m0 = tx, m1 = tx + 32;
        float a0[4] = {}, a1[4] = {};
        const float4* s4 = (const float4*)sx;
        #pragma unroll 4
        for (int k4 = 0; k4 < 32; k4++) {
            float4 kr[4];
            #pragma unroll
            for (int i = 0; i < 4; i++) kr[i] = s4[(r0+i)*32 + k4];
            #pragma unroll
            for (int s = 0; s < 4; s++) {
                int k = 4*k4 + s;
                float mv0 = MkT[k*65 + m0];
                float mv1 = MkT[k*65 + m1];
                #pragma unroll
                for (int i = 0; i < 4; i++) {
                    float kv = ((const float*)&kr[i])[s];
                    a0[i] = fmaf(kv, mv0, a0[i]);
                    a1[i] = fmaf(kv, mv1, a1[i]);
                }
            }
        }
        #pragma unroll
        for (int i = 0; i < 4; i++) {
            float v0 = a0[i];
            float v1 = (m1 < M_) ? a1[i] : -1e30f;
            float mx = fmaxf(v0, v1);
            #pragma unroll
            for (int o = 16; o >= 1; o >>= 1) mx = fmaxf(mx, __shfl_xor_sync(0xffffffffu, mx, o));
            float e0 = __expf(v0 - mx);
            float e1 = (m1 < M_) ? __expf(v1 - mx) : 0.f;
            float s = e0 + e1;
            #pragma unroll
            for (int o = 16; o >= 1; o >>= 1) s += __shfl_xor_sync(0xffffffffu, s, o);
            float inv = __frcp_rn(s);
            int row = rbase + r0 + i;
            g_wtab[row*WSTR + m0] = e0 * inv;
            g_wtab[row*WSTR + m1] = e1 * inv;   // zero in pad region
        }
    }
}

// =====================================================================
// Kernel B: sequential scan; grid (B, 2 d-halves) x 512 threads.
// Depth-2 prefetch of table gathers to hide L2 latency.
// =====================================================================
extern "C" __global__ void __launch_bounds__(512)
kB_scan(const int* __restrict__ skills, const int* __restrict__ responses,
        const float* __restrict__ Mv0)
{
    __shared__ int s_sk[L_], s_x[L_];
    const int b   = blockIdx.x;
    const int tid = threadIdx.x;

    for (int t = tid; t < L_; t += 512) {
        int sk = skills[b*L_ + t];
        int r  = responses[b*L_ + t];
        int mr = (r > -1) ? r : 0;
        s_sk[t] = sk;
        s_x[t]  = sk + NS_ * mr;
    }
    __syncthreads();

    const int mg  = tid & 7;
    const int dl  = tid >> 3;
    const int d   = blockIdx.y * 64 + dl;
    const int mbase = mg * 8;

    float mv[8];
    #pragma unroll
    for (int i = 0; i < 8; i++) {
        int m = mbase + i;
        mv[i] = (m < M_) ? Mv0[m*D_ + d] : 0.f;
    }

    float* rp = g_read + (size_t)b*L_*D_ + d;

    float ev0, av0, ev1, av1;
    float4 w0[2], w1[2];
    {
        int xx = s_x[0], kk = s_sk[0];
        ev0 = __ldg(&g_etab[(size_t)xx*D_ + d]);
        av0 = __ldg(&g_atab[(size_t)xx*D_ + d]);
        const float4* wq = (const float4*)(g_wtab + kk*WSTR + mbase);
        w0[0] = __ldg(wq); w0[1] = __ldg(wq + 1);
        xx = s_x[1]; kk = s_sk[1];
        ev1 = __ldg(&g_etab[(size_t)xx*D_ + d]);
        av1 = __ldg(&g_atab[(size_t)xx*D_ + d]);
        wq = (const float4*)(g_wtab + kk*WSTR + mbase);
        w1[0] = __ldg(wq); w1[1] = __ldg(wq + 1);
    }

    for (int t = 0; t < L_; t++) {
        float ev2 = 0.f, av2 = 0.f;
        float4 w2[2] = {};
        if (t + 2 < L_) {
            int xx = s_x[t+2], kk = s_sk[t+2];
            ev2 = __ldg(&g_etab[(size_t)xx*D_ + d]);
            av2 = __ldg(&g_atab[(size_t)xx*D_ + d]);
            const float4* wq = (const float4*)(g_wtab + kk*WSTR + mbase);
            w2[0] = __ldg(wq); w2[1] = __ldg(wq + 1);
        }

        float rda[2] = {0.f, 0.f};
        #pragma unroll
        for (int j = 0; j < 2; j++) {
            float wv[4] = {w0[j].x, w0[j].y, w0[j].z, w0[j].w};
            #pragma unroll
            for (int s = 0; s < 4; s++) {
                int i = j*4 + s;
                float w = wv[s];
                rda[j] = fmaf(w, mv[i], rda[j]);   // read uses PRE-update Mv
                float g = fmaf(-ev0, mv[i], av0);  // a - e*mv
                mv[i] = fmaf(w, g, mv[i]);         // mv += w*(a - e*mv)
            }
        }
        float rd = rda[0] + rda[1];
        rd += __shfl_xor_sync(0xffffffffu, rd, 1);
        rd += __shfl_xor_sync(0xffffffffu, rd, 2);
        rd += __shfl_xor_sync(0xffffffffu, rd, 4);
        if (mg == 0) rp[t*D_] = rd;

        ev0 = ev1; av0 = av1; w0[0] = w1[0]; w0[1] = w1[1];
        ev1 = ev2; av1 = av2; w1[0] = w2[0]; w1[1] = w2[1];
    }
}

// =====================================================================
// Kernel C: f = tanh(read @ f_Wr^T + kf_tab[skill] + f_b); p = sigmoid(f.p_W+p_b)
// 400 blocks x 256 threads, 32 rows/block; 80KB smem -> 2 blocks/SM.
// Weight staging = straight copy of g_frT.
// =====================================================================
extern "C" __global__ void __launch_bounds__(256, 2)
kC_out(const int* __restrict__ skills,
       const float* __restrict__ f_b,
       const float* __restrict__ p_W, const float* __restrict__ p_b,
       float* __restrict__ out)
{
    extern __shared__ float sm[];
    float* hx  = sm;                 // 32*128 read tile (16KB)
    float* fWT = sm + 32*D_;         // 128*128 transposed weights (64KB)
    __shared__ int s_sk[32];

    const int tid  = threadIdx.x;
    const int row0 = blockIdx.x * 32;

    if (tid < 32) s_sk[tid] = skills[row0 + tid];
    {
        float4* w4 = (float4*)fWT;
        const float4* WT4 = (const float4*)g_frT;
        #pragma unroll
        for (int i = 0; i < 16; i++) w4[tid + i*256] = __ldg(&WT4[tid + i*256]);
    }
    {
        float4* h4 = (float4*)hx;
        const float4* rd4 = (const float4*)g_read;
        for (int u = tid; u < 32*32; u += 256) {
            int r = u >> 5, c = u & 31;
            h4[r*32 + c] = rd4[(size_t)(row0 + r)*32 + c];
        }
    }
    __syncthreads();

    const int tx = tid & 31, ty = tid >> 5;
    const int r0 = ty * 4, c0 = tx * 4;

    float acc[4][4] = {};
    const float4* h4 = (const float4*)hx;
    #pragma unroll 4
    for (int k4 = 0; k4 < 32; k4++) {
        float4 hr[4];
        #pragma unroll
        for (int i = 0; i < 4; i++) hr[i] = h4[(r0+i)*32 + k4];
        #pragma unroll
        for (int s = 0; s < 4; s++) {
            int k = k4*4 + s;
            float4 w = *(const float4*)&fWT[k*D_ + c0];
            #pragma unroll
            for (int i = 0; i < 4; i++) {
                float hv = ((const float*)&hr[i])[s];
                acc[i][0] = fmaf(hv, w.x, acc[i][0]);
                acc[i][1] = fmaf(hv, w.y, acc[i][1]);
                acc[i][2] = fmaf(hv, w.z, acc[i][2]);
                acc[i][3] = fmaf(hv, w.w, acc[i][3]);
            }
        }
    }
    float4 fb = *(const float4*)&f_b[c0];
    float4 pw = *(const float4*)&p_W[c0];
    float pb = p_b[0];
    #pragma unroll
    for (int i = 0; i < 4; i++) {
        int row = row0 + r0 + i;
        int sk = s_sk[r0 + i];
        float4 kf = *(const float4*)&g_kftab[(size_t)sk*D_ + c0];
        float f0 = ftanh(acc[i][0] + kf.x + fb.x);
        float f1 = ftanh(acc[i][1] + kf.y + fb.y);
        float f2 = ftanh(acc[i][2] + kf.z + fb.z);
        float f3 = ftanh(acc[i][3] + kf.w + fb.w);
        float pp = f0*pw.x + f1*pw.y + f2*pw.z + f3*pw.w;
        #pragma unroll
        for (int o = 16; o >= 1; o >>= 1) pp += __shfl_xor_sync(0xffffffffu, pp, o);
        if (tx == 0) {
            int bb = row / L_, t = row % L_;
            if (t >= 1) out[bb*(L_-1) + (t-1)] = fsigmoid(pp + pb);
        }
    }
}

// =====================================================================
extern "C" void kernel_launch(void* const* d_in, const int* in_sizes, int n_in,
                              void* d_out, int out_size)
{
    const int*   skills    = (const int*)  d_in[0];
    const int*   responses = (const int*)  d_in[1];
    const float* k_emb     = (const float*)d_in[2];
    const float* v_emb     = (const float*)d_in[3];
    const float* Mk        = (const float*)d_in[4];
    const float* Mv0       = (const float*)d_in[5];
    const float* e_W       = (const float*)d_in[6];
    const float* e_b       = (const float*)d_in[7];
    const float* a_W       = (const float*)d_in[8];
    const float* a_b       = (const float*)d_in[9];
    const float* f_W       = (const float*)d_in[10];
    const float* f_b       = (const float*)d_in[11];
    const float* p_W       = (const float*)d_in[12];
    const float* p_b       = (const float*)d_in[13];
    float* out = (float*)d_out;

    const size_t SZA = (size_t)(32*D_ + D_*D_) * sizeof(float);   // 81920
    const size_t SZC = (size_t)(32*D_ + D_*D_) * sizeof(float);   // 81920

    cudaFuncSetAttribute(kA_tables, cudaFuncAttributeMaxDynamicSharedMemorySize, (int)SZA);
    cudaFuncSetAttribute(kC_out,    cudaFuncAttributeMaxDynamicSharedMemorySize, (int)SZC);

    k0_transpose<<<dim3(16, 4), 256>>>(e_W, a_W, f_W);
    kA_tables<<<190, 256, SZA>>>(k_emb, v_emb, Mk, e_b, a_b);
    kB_scan<<<dim3(B_, 2), 512>>>(skills, responses, Mv0);
    kC_out<<<BL_/32, 256, SZC>>>(skills, f_b, p_W, p_b, out);
}

// round 7
// speedup vs baseline: 2.0862x; 2.0862x over previous
#include <cuda_runtime.h>

#define B_  64
#define L_  200
#define NS_ 1000
#define D_  128
#define M_  50
#define BL_ (B_*L_)
#define WSTR 64   // padded w-row stride (slots 50..63 zero)

// -------- scratch (device globals; no allocation allowed) --------
__device__ float g_eWT[D_*D_];        // e_W transposed [k][d]
__device__ float g_aWT[D_*D_];        // a_W transposed
__device__ float g_frT[D_*D_];        // read-half of f_W transposed [k][d]
__device__ float g_fkT[D_*D_];        // k-half of f_W transposed
__device__ float g_wtab[1024*WSTR];   // softmax weights per skill (padded)
__device__ float g_etab[2016*D_];     // sigmoid erase per x
__device__ float g_atab[2016*D_];     // tanh add per x
__device__ float g_kftab[1024*D_];    // k_emb[s] @ f_Wk^T (no bias/act)
__device__ float g_read[BL_*D_];      // read vectors

__device__ __forceinline__ float fsigmoid(float x){ return 1.f/(1.f+__expf(-x)); }
__device__ __forceinline__ float ftanh(float x){ float y; asm("tanh.approx.f32 %0, %1;":"=f"(y):"f"(x)); return y; }

// =====================================================================
// Kernel 0: transpose the 4 weight matrices once (tiled, conflict-free).
// grid (16, 4): blockIdx.y = matrix, blockIdx.x = 32x32 tile. 256 thr.
// =====================================================================
extern "C" __global__ void __launch_bounds__(256)
k0_transpose(const float* __restrict__ e_W, const float* __restrict__ a_W,
             const float* __restrict__ f_W)
{
    __shared__ float tile[32][33];
    const int m  = blockIdx.y;
    const int tb = blockIdx.x;
    const int d0 = (tb & 3) * 32;       // src row block
    const int k0 = (tb >> 2) * 32;      // src col block
    const int c  = threadIdx.x & 31;
    const int rb = threadIdx.x >> 5;    // 8 rows per pass

    const float* src; int stride, off; float* dst;
    if      (m == 0) { src = e_W; stride = D_;   off = 0;   dst = g_eWT; }
    else if (m == 1) { src = a_W; stride = D_;   off = 0;   dst = g_aWT; }
    else if (m == 2) { src = f_W; stride = 2*D_; off = 0;   dst = g_frT; }
    else             { src = f_W; stride = 2*D_; off = D_;  dst = g_fkT; }

    #pragma unroll
    for (int p = 0; p < 4; p++) {
        int r = rb + p*8;
        tile[r][c] = src[(size_t)(d0 + r)*stride + off + k0 + c];
    }
    __syncthreads();
    #pragma unroll
    for (int p = 0; p < 4; p++) {
        int r = rb + p*8;
        dst[(size_t)(k0 + r)*D_ + d0 + c] = tile[c][r];
    }
}

// =====================================================================
// Kernel A: build all tables. 190 blocks x 256 threads, 80KB smem
//  -> 2 blocks/SM. Weight staging = straight float4 copy of transposed
//  gmem weights. Block types:
//   [0,63) e-table  [63,126) a-table  [126,158) w-table  [158,190) kf-table
// =====================================================================
extern "C" __global__ void __launch_bounds__(256, 2)
kA_tables(const float* __restrict__ k_emb, const float* __restrict__ v_emb,
          const float* __restrict__ Mk,
          const float* __restrict__ e_b, const float* __restrict__ a_b)
{
    extern __shared__ float sm[];
    float* sx = sm;                 // 32*128 activation tile (16KB)
    float* sw = sm + 32*D_;         // 128*128 transposed weights (64KB)
    const int tid = threadIdx.x;
    const int tx = tid & 31, ty = tid >> 5;
    const int r0 = ty * 4, c0 = tx * 4;
    const int bid = blockIdx.x;

    if (bid < 126 || bid >= 158) {
        // ------- e-table / a-table / kf-table (dense 128x128 GEMM) -------
        const int type  = (bid < 63) ? 0 : (bid < 126) ? 1 : 2;
        const int rbase = (type == 0 ? bid : type == 1 ? bid - 63 : bid - 158) * 32;
        const float* WT = (type == 0) ? g_eWT : (type == 1) ? g_aWT : g_fkT;
        const float* xs = (type == 2) ? k_emb : v_emb;
        const int rmax  = (type == 2) ? NS_ - 1 : 2*NS_ - 1;

        {   // stage transposed weights: straight copy, conflict-free
            float4* sw4 = (float4*)sw;
            const float4* WT4 = (const float4*)WT;
            #pragma unroll
            for (int i = 0; i < 16; i++) sw4[tid + i*256] = __ldg(&WT4[tid + i*256]);
        }
        {   // gather 32 activation rows
            float4* s4 = (float4*)sx;
            const float4* xs4 = (const float4*)xs;
            for (int u = tid; u < 32*32; u += 256) {
                int r = u >> 5, cc = u & 31;
                int rr = min(rbase + r, rmax);
                s4[r*32 + cc] = __ldg(&xs4[(size_t)rr*32 + cc]);
            }
        }
        __syncthreads();

        float acc[4][4] = {};
        const float4* s4 = (const float4*)sx;
        #pragma unroll 4
        for (int k4 = 0; k4 < 32; k4++) {
            float4 vr[4];
            #pragma unroll
            for (int i = 0; i < 4; i++) vr[i] = s4[(r0+i)*32 + k4];
            #pragma unroll
            for (int s = 0; s < 4; s++) {
                int k = 4*k4 + s;
                float4 w = *(const float4*)&sw[k*D_ + c0];
                #pragma unroll
                for (int i = 0; i < 4; i++) {
                    float vv = ((const float*)&vr[i])[s];
                    acc[i][0] = fmaf(vv, w.x, acc[i][0]);
                    acc[i][1] = fmaf(vv, w.y, acc[i][1]);
                    acc[i][2] = fmaf(vv, w.z, acc[i][2]);
                    acc[i][3] = fmaf(vv, w.w, acc[i][3]);
                }
            }
        }
        #pragma unroll
        for (int i = 0; i < 4; i++) {
            int row = rbase + r0 + i;
            float4 o;
            if (type == 0) {
                float4 bb = *(const float4*)&e_b[c0];
                o.x = fsigmoid(acc[i][0] + bb.x); o.y = fsigmoid(acc[i][1] + bb.y);
                o.z = fsigmoid(acc[i][2] + bb.z); o.w = fsigmoid(acc[i][3] + bb.w);
                *(float4*)&g_etab[(size_t)row*D_ + c0] = o;
            } else if (type == 1) {
                float4 bb = *(const float4*)&a_b[c0];
                o.x = ftanh(acc[i][0] + bb.x); o.y = ftanh(acc[i][1] + bb.y);
                o.z = ftanh(acc[i][2] + bb.z); o.w = ftanh(acc[i][3] + bb.w);
                *(float4*)&g_atab[(size_t)row*D_ + c0] = o;
            } else {
                o.x = acc[i][0]; o.y = acc[i][1]; o.z = acc[i][2]; o.w = acc[i][3];
                *(float4*)&g_kftab[(size_t)row*D_ + c0] = o;
            }
        }
    } else {
        // ---------------- w (softmax) table ----------------
        const int rbase = (bid - 126) * 32;
        float* MkT = sw;                      // 128*65 (pad 65: conflict-free)
        for (int i = tid; i < M_*D_; i += 256) {
            int m = i >> 7, k = i & 127;
            MkT[k*65 + m] = Mk[i];
        }
        for (int i = tid; i < D_*14; i += 256) {
            int k = i / 14, m = 50 + (i % 14);
            MkT[k*65 + m] = 0.f;
        }
        {
            float4* s4 = (float4*)sx;
            const float4* ke4 = (const float4*)k_emb;
            for (int u = tid; u < 32*32; u += 256) {
                int r = u >> 5, cc = u & 31;
                int rr = min(rbase + r, NS_ - 1);
                s4[r*32 + cc] = __ldg(&ke4[(size_t)rr*32 + cc]);
            }
        }
        __syncthreads();

        const int m0 = tx, m1 = tx + 32;
        float a0[4] = {}, a1[4] = {};
        const float4* s4 = (const float4*)sx;
        #pragma unroll 4
        for (int k4 = 0; k4 < 32; k4++) {
            float4 kr[4];
            #pragma unroll
            for (int i = 0; i < 4; i++) kr[i] = s4[(r0+i)*32 + k4];
            #pragma unroll
            for (int s = 0; s < 4; s++) {
                int k = 4*k4 + s;
                float mv0 = MkT[k*65 + m0];
                float mv1 = MkT[k*65 + m1];
                #pragma unroll
                for (int i = 0; i < 4; i++) {
                    float kv = ((const float*)&kr[i])[s];
                    a0[i] = fmaf(kv, mv0, a0[i]);
                    a1[i] = fmaf(kv, mv1, a1[i]);
                }
            }
        }
        #pragma unroll
        for (int i = 0; i < 4; i++) {
            float v0 = a0[i];
            float v1 = (m1 < M_) ? a1[i] : -1e30f;
            float mx = fmaxf(v0, v1);
            #pragma unroll
            for (int o = 16; o >= 1; o >>= 1) mx = fmaxf(mx, __shfl_xor_sync(0xffffffffu, mx, o));
            float e0 = __expf(v0 - mx);
            float e1 = (m1 < M_) ? __expf(v1 - mx) : 0.f;
            float s = e0 + e1;
            #pragma unroll
            for (int o = 16; o >= 1; o >>= 1) s += __shfl_xor_sync(0xffffffffu, s, o);
            float inv = __frcp_rn(s);
            int row = rbase + r0 + i;
            g_wtab[row*WSTR + m0] = e0 * inv;
            g_wtab[row*WSTR + m1] = e1 * inv;   // zero in pad region
        }
    }
}

// =====================================================================
// Kernel B: sequential scan; grid (B, 2 d-halves) x 512 threads.
// ALL w/e/a rows for this block staged into smem up front (bulk copy,
// full MLP); the 200-step loop then reads only smem. 154KB dynamic smem
// -> 1 block/SM (128 blocks ~ one wave).
// =====================================================================
extern "C" __global__ void __launch_bounds__(512)
kB_scan(const int* __restrict__ skills, const int* __restrict__ responses,
        const float* __restrict__ Mv0)
{
    extern __shared__ float sb[];
    float* s_w = sb;               // L*64
    float* s_e = sb + L_*64;       // L*64 (this block's 64-d slice)
    float* s_a = sb + 2*L_*64;     // L*64
    __shared__ int s_x[L_], s_sk[L_];

    const int b   = blockIdx.x;
    const int tid = threadIdx.x;
    const int dhalf = blockIdx.y;        // 0 or 1

    for (int t = tid; t < L_; t += 512) {
        int sk = skills[b*L_ + t];
        int r  = responses[b*L_ + t];
        int mr = (r > -1) ? r : 0;
        s_sk[t] = sk;
        s_x[t]  = sk + NS_ * mr;
    }
    __syncthreads();

    {   // bulk stage: 16 float4 per t per table
        float4* sw4 = (float4*)s_w;
        float4* se4 = (float4*)s_e;
        float4* sa4 = (float4*)s_a;
        const float4* wt4 = (const float4*)g_wtab;
        const float4* et4 = (const float4*)g_etab;
        const float4* at4 = (const float4*)g_atab;
        const int dbase4 = dhalf * 16;   // d offset in float4 units
        for (int u = tid; u < L_*16; u += 512) {
            int t = u >> 4, c = u & 15;
            int xx = s_x[t], kk = s_sk[t];
            sw4[u] = __ldg(&wt4[kk*16 + c]);
            se4[u] = __ldg(&et4[(size_t)xx*32 + dbase4 + c]);
            sa4[u] = __ldg(&at4[(size_t)xx*32 + dbase4 + c]);
        }
    }
    __syncthreads();

    const int mg  = tid & 7;
    const int dl  = tid >> 3;
    const int d   = dhalf * 64 + dl;
    const int mbase = mg * 8;

    float mv[8];
    #pragma unroll
    for (int i = 0; i < 8; i++) {
        int m = mbase + i;
        mv[i] = (m < M_) ? Mv0[m*D_ + d] : 0.f;
    }

    float* rp = g_read + (size_t)b*L_*D_ + d;

    #pragma unroll 2
    for (int t = 0; t < L_; t++) {
        float ev = s_e[t*64 + dl];
        float av = s_a[t*64 + dl];
        float4 wa = *(const float4*)&s_w[t*64 + mbase];
        float4 wb = *(const float4*)&s_w[t*64 + mbase + 4];

        float rda = 0.f, rdb = 0.f;
        {
            float wv[4] = {wa.x, wa.y, wa.z, wa.w};
            #pragma unroll
            for (int s = 0; s < 4; s++) {
                float w = wv[s];
                rda = fmaf(w, mv[s], rda);          // read uses PRE-update Mv
                float g = fmaf(-ev, mv[s], av);     // a - e*mv
                mv[s] = fmaf(w, g, mv[s]);          // mv += w*(a - e*mv)
            }
        }
        {
            float wv[4] = {wb.x, wb.y, wb.z, wb.w};
            #pragma unroll
            for (int s = 0; s < 4; s++) {
                float w = wv[s];
                rdb = fmaf(w, mv[4+s], rdb);
                float g = fmaf(-ev, mv[4+s], av);
                mv[4+s] = fmaf(w, g, mv[4+s]);
            }
        }
        float rd = rda + rdb;
        rd += __shfl_xor_sync(0xffffffffu, rd, 1);
        rd += __shfl_xor_sync(0xffffffffu, rd, 2);
        rd += __shfl_xor_sync(0xffffffffu, rd, 4);
        if (mg == 0) rp[t*D_] = rd;
    }
}

// =====================================================================
// Kernel C: f = tanh(read @ f_Wr^T + kf_tab[skill] + f_b); p = sigmoid(f.p_W+p_b)
// 200 blocks x 512 threads, 64 rows/block; 96KB smem -> 2 blocks/SM.
// =====================================================================
extern "C" __global__ void __launch_bounds__(512, 2)
kC_out(const int* __restrict__ skills,
       const float* __restrict__ f_b,
       const float* __restrict__ p_W, const float* __restrict__ p_b,
       float* __restrict__ out)
{
    extern __shared__ float sm[];
    float* hx  = sm;                 // 64*128 read tile (32KB)
    float* fWT = sm + 64*D_;         // 128*128 transposed weights (64KB)
    __shared__ int s_sk[64];

    const int tid  = threadIdx.x;
    const int row0 = blockIdx.x * 64;

    if (tid < 64) s_sk[tid] = skills[row0 + tid];
    {
        float4* w4 = (float4*)fWT;
        const float4* WT4 = (const float4*)g_frT;
        #pragma unroll
        for (int i = 0; i < 8; i++) w4[tid + i*512] = __ldg(&WT4[tid + i*512]);
    }
    {
        float4* h4 = (float4*)hx;
        const float4* rd4 = (const float4*)g_read;
        #pragma unroll
        for (int i = 0; i < 4; i++) h4[tid + i*512] = __ldg(&rd4[(size_t)row0*32 + tid + i*512]);
    }
    __syncthreads();

    const int tx = tid & 31, ty = tid >> 5;
    const int r0 = ty * 4, c0 = tx * 4;

    float acc[4][4] = {};
    const float4* h4 = (const float4*)hx;
    #pragma unroll 4
    for (int k4 = 0; k4 < 32; k4++) {
        float4 hr[4];
        #pragma unroll
        for (int i = 0; i < 4; i++) hr[i] = h4[(r0+i)*32 + k4];
        #pragma unroll
        for (int s = 0; s < 4; s++) {
            int k = k4*4 + s;
            float4 w = *(const float4*)&fWT[k*D_ + c0];
            #pragma unroll
            for (int i = 0; i < 4; i++) {
                float hv = ((const float*)&hr[i])[s];
                acc[i][0] = fmaf(hv, w.x, acc[i][0]);
                acc[i][1] = fmaf(hv, w.y, acc[i][1]);
                acc[i][2] = fmaf(hv, w.z, acc[i][2]);
                acc[i][3] = fmaf(hv, w.w, acc[i][3]);
            }
        }
    }
    float4 fb = *(const float4*)&f_b[c0];
    float4 pw = *(const float4*)&p_W[c0];
    float pb = p_b[0];
    #pragma unroll
    for (int i = 0; i < 4; i++) {
        int row = row0 + r0 + i;
        int sk = s_sk[r0 + i];
        float4 kf = *(const float4*)&g_kftab[(size_t)sk*D_ + c0];
        float f0 = ftanh(acc[i][0] + kf.x + fb.x);
        float f1 = ftanh(acc[i][1] + kf.y + fb.y);
        float f2 = ftanh(acc[i][2] + kf.z + fb.z);
        float f3 = ftanh(acc[i][3] + kf.w + fb.w);
        float pp = f0*pw.x + f1*pw.y + f2*pw.z + f3*pw.w;
        #pragma unroll
        for (int o = 16; o >= 1; o >>= 1) pp += __shfl_xor_sync(0xffffffffu, pp, o);
        if (tx == 0) {
            int bb = row / L_, t = row % L_;
            if (t >= 1) out[bb*(L_-1) + (t-1)] = fsigmoid(pp + pb);
        }
    }
}

// =====================================================================
extern "C" void kernel_launch(void* const* d_in, const int* in_sizes, int n_in,
                              void* d_out, int out_size)
{
    const int*   skills    = (const int*)  d_in[0];
    const int*   responses = (const int*)  d_in[1];
    const float* k_emb     = (const float*)d_in[2];
    const float* v_emb     = (const float*)d_in[3];
    const float* Mk        = (const float*)d_in[4];
    const float* Mv0       = (const float*)d_in[5];
    const float* e_W       = (const float*)d_in[6];
    const float* e_b       = (const float*)d_in[7];
    const float* a_W       = (const float*)d_in[8];
    const float* a_b       = (const float*)d_in[9];
    const float* f_W       = (const float*)d_in[10];
    const float* f_b       = (const float*)d_in[11];
    const float* p_W       = (const float*)d_in[12];
    const float* p_b       = (const float*)d_in[13];
    float* out = (float*)d_out;

    const size_t SZA = (size_t)(32*D_ + D_*D_) * sizeof(float);   //  81920
    const size_t SZB = (size_t)(3*L_*64) * sizeof(float);         // 153600
    const size_t SZC = (size_t)(64*D_ + D_*D_) * sizeof(float);   //  98304

    cudaFuncSetAttribute(kA_tables, cudaFuncAttributeMaxDynamicSharedMemorySize, (int)SZA);
    cudaFuncSetAttribute(kB_scan,   cudaFuncAttributeMaxDynamicSharedMemorySize, (int)SZB);
    cudaFuncSetAttribute(kC_out,    cudaFuncAttributeMaxDynamicSharedMemorySize, (int)SZC);

    k0_transpose<<<dim3(16, 4), 256>>>(e_W, a_W, f_W);
    kA_tables<<<190, 256, SZA>>>(k_emb, v_emb, Mk, e_b, a_b);
    kB_scan<<<dim3(B_, 2), 512, SZB>>>(skills, responses, Mv0);
    kC_out<<<BL_/64, 512, SZC>>>(skills, f_b, p_W, p_b, out);
}

// round 8
// speedup vs baseline: 2.1115x; 1.0121x over previous
#include <cuda_runtime.h>

#define B_  64
#define L_  200
#define NS_ 1000
#define D_  128
#define M_  50
#define BL_ (B_*L_)
#define WSTR 64   // padded w-row stride (slots 50..63 zero)

// -------- scratch (device globals; no allocation allowed) --------
__device__ float g_eWT[D_*D_];        // e_W transposed [k][d]
__device__ float g_aWT[D_*D_];        // a_W transposed
__device__ float g_frT[D_*D_];        // read-half of f_W transposed [k][d]
__device__ float g_fkT[D_*D_];        // k-half of f_W transposed
__device__ float g_wtab[1024*WSTR];   // softmax weights per skill (padded)
__device__ float g_etab[2048*D_];     // sigmoid erase per x (rows>=2000 junk)
__device__ float g_atab[2048*D_];     // tanh add per x
__device__ float g_kftab[1024*D_];    // k_emb[s] @ f_Wk^T (no bias/act)
__device__ float g_read[BL_*D_];      // read vectors

__device__ __forceinline__ float fsigmoid(float x){ return 1.f/(1.f+__expf(-x)); }
__device__ __forceinline__ float ftanh(float x){ float y; asm("tanh.approx.f32 %0, %1;":"=f"(y):"f"(x)); return y; }

// =====================================================================
// Kernel 0: transpose the 4 weight matrices once (tiled, conflict-free).
// grid (16, 4): blockIdx.y = matrix, blockIdx.x = 32x32 tile. 256 thr.
// =====================================================================
extern "C" __global__ void __launch_bounds__(256)
k0_transpose(const float* __restrict__ e_W, const float* __restrict__ a_W,
             const float* __restrict__ f_W)
{
    __shared__ float tile[32][33];
    const int m  = blockIdx.y;
    const int tb = blockIdx.x;
    const int d0 = (tb & 3) * 32;       // src row block
    const int k0 = (tb >> 2) * 32;      // src col block
    const int c  = threadIdx.x & 31;
    const int rb = threadIdx.x >> 5;    // 8 rows per pass

    const float* src; int stride, off; float* dst;
    if      (m == 0) { src = e_W; stride = D_;   off = 0;   dst = g_eWT; }
    else if (m == 1) { src = a_W; stride = D_;   off = 0;   dst = g_aWT; }
    else if (m == 2) { src = f_W; stride = 2*D_; off = 0;   dst = g_frT; }
    else             { src = f_W; stride = 2*D_; off = D_;  dst = g_fkT; }

    #pragma unroll
    for (int p = 0; p < 4; p++) {
        int r = rb + p*8;
        tile[r][c] = src[(size_t)(d0 + r)*stride + off + k0 + c];
    }
    __syncthreads();
    #pragma unroll
    for (int p = 0; p < 4; p++) {
        int r = rb + p*8;
        dst[(size_t)(k0 + r)*D_ + d0 + c] = tile[c][r];
    }
}

// =====================================================================
// Kernel A: build all tables. 96 blocks x 512 threads, 96KB smem
//  -> 2 blocks/SM. 64 rows/block. Block types:
//   [0,32) e-table  [32,64) a-table  [64,80) w-table  [80,96) kf-table
// =====================================================================
extern "C" __global__ void __launch_bounds__(512, 2)
kA_tables(const float* __restrict__ k_emb, const float* __restrict__ v_emb,
          const float* __restrict__ Mk,
          const float* __restrict__ e_b, const float* __restrict__ a_b)
{
    extern __shared__ float sm[];
    float* sx = sm;                 // 64*128 activation tile (32KB)
    float* sw = sm + 64*D_;         // 128*128 transposed weights (64KB)
    const int tid = threadIdx.x;
    const int tx = tid & 31, ty = tid >> 5;   // ty 0..15
    const int r0 = ty * 4, c0 = tx * 4;
    const int bid = blockIdx.x;

    if (bid < 64 || bid >= 80) {
        // ------- e-table / a-table / kf-table (dense GEMM, 64 rows) -------
        const int type  = (bid < 32) ? 0 : (bid < 64) ? 1 : 2;
        const int rbase = (type == 0 ? bid : type == 1 ? bid - 32 : bid - 80) * 64;
        const float* WT = (type == 0) ? g_eWT : (type == 1) ? g_aWT : g_fkT;
        const float* xs = (type == 2) ? k_emb : v_emb;
        const int rmax  = (type == 2) ? NS_ - 1 : 2*NS_ - 1;

        {   // stage transposed weights: straight copy, conflict-free
            float4* sw4 = (float4*)sw;
            const float4* WT4 = (const float4*)WT;
            #pragma unroll
            for (int i = 0; i < 8; i++) sw4[tid + i*512] = __ldg(&WT4[tid + i*512]);
        }
        {   // gather 64 activation rows
            float4* s4 = (float4*)sx;
            const float4* xs4 = (const float4*)xs;
            #pragma unroll
            for (int i = 0; i < 4; i++) {
                int u = tid + i*512;
                int r = u >> 5, cc = u & 31;
                int rr = min(rbase + r, rmax);
                s4[u] = __ldg(&xs4[(size_t)rr*32 + cc]);
            }
        }
        __syncthreads();

        float acc[4][4] = {};
        const float4* s4 = (const float4*)sx;
        #pragma unroll 4
        for (int k4 = 0; k4 < 32; k4++) {
            float4 vr[4];
            #pragma unroll
            for (int i = 0; i < 4; i++) vr[i] = s4[(r0+i)*32 + k4];
            #pragma unroll
            for (int s = 0; s < 4; s++) {
                int k = 4*k4 + s;
                float4 w = *(const float4*)&sw[k*D_ + c0];
                #pragma unroll
                for (int i = 0; i < 4; i++) {
                    float vv = ((const float*)&vr[i])[s];
                    acc[i][0] = fmaf(vv, w.x, acc[i][0]);
                    acc[i][1] = fmaf(vv, w.y, acc[i][1]);
                    acc[i][2] = fmaf(vv, w.z, acc[i][2]);
                    acc[i][3] = fmaf(vv, w.w, acc[i][3]);
                }
            }
        }
        #pragma unroll
        for (int i = 0; i < 4; i++) {
            int row = rbase + r0 + i;
            float4 o;
            if (type == 0) {
                float4 bb = *(const float4*)&e_b[c0];
                o.x = fsigmoid(acc[i][0] + bb.x); o.y = fsigmoid(acc[i][1] + bb.y);
                o.z = fsigmoid(acc[i][2] + bb.z); o.w = fsigmoid(acc[i][3] + bb.w);
                *(float4*)&g_etab[(size_t)row*D_ + c0] = o;
            } else if (type == 1) {
                float4 bb = *(const float4*)&a_b[c0];
                o.x = ftanh(acc[i][0] + bb.x); o.y = ftanh(acc[i][1] + bb.y);
                o.z = ftanh(acc[i][2] + bb.z); o.w = ftanh(acc[i][3] + bb.w);
                *(float4*)&g_atab[(size_t)row*D_ + c0] = o;
            } else {
                o.x = acc[i][0]; o.y = acc[i][1]; o.z = acc[i][2]; o.w = acc[i][3];
                *(float4*)&g_kftab[(size_t)row*D_ + c0] = o;
            }
        }
    } else {
        // ---------------- w (softmax) table, 64 rows ----------------
        const int rbase = (bid - 64) * 64;
        float* MkT = sw;                      // 128*65 (pad 65: conflict-free)
        for (int i = tid; i < M_*D_; i += 512) {
            int m = i >> 7, k = i & 127;
            MkT[k*65 + m] = Mk[i];
        }
        for (int i = tid; i < D_*14; i += 512) {
            int k = i / 14, m = 50 + (i % 14);
            MkT[k*65 + m] = 0.f;
        }
        {
            float4* s4 = (float4*)sx;
            const float4* ke4 = (const float4*)k_emb;
            #pragma unroll
            for (int i = 0; i < 4; i++) {
                int u = tid + i*512;
                int r = u >> 5, cc = u & 31;
                int rr = min(rbase + r, NS_ - 1);
                s4[u] = __ldg(&ke4[(size_t)rr*32 + cc]);
            }
        }
        __syncthreads();

        const int m0 = tx, m1 = tx + 32;
        float a0[4] = {}, a1[4] = {};
        const float4* s4 = (const float4*)sx;
        #pragma unroll 4
        for (int k4 = 0; k4 < 32; k4++) {
            float4 kr[4];
            #pragma unroll
            for (int i = 0; i < 4; i++) kr[i] = s4[(r0+i)*32 + k4];
            #pragma unroll
            for (int s = 0; s < 4; s++) {
                int k = 4*k4 + s;
                float mv0 = MkT[k*65 + m0];
                float mv1 = MkT[k*65 + m1];
                #pragma unroll
                for (int i = 0; i < 4; i++) {
                    float kv = ((const float*)&kr[i])[s];
                    a0[i] = fmaf(kv, mv0, a0[i]);
                    a1[i] = fmaf(kv, mv1, a1[i]);
                }
            }
        }
        #pragma unroll
        for (int i = 0; i < 4; i++) {
            float v0 = a0[i];
            float v1 = (m1 < M_) ? a1[i] : -1e30f;
            float mx = fmaxf(v0, v1);
            #pragma unroll
            for (int o = 16; o >= 1; o >>= 1) mx = fmaxf(mx, __shfl_xor_sync(0xffffffffu, mx, o));
            float e0 = __expf(v0 - mx);
            float e1 = (m1 < M_) ? __expf(v1 - mx) : 0.f;
            float s = e0 + e1;
            #pragma unroll
            for (int o = 16; o >= 1; o >>= 1) s += __shfl_xor_sync(0xffffffffu, s, o);
            float inv = __frcp_rn(s);
            int row = rbase + r0 + i;
            g_wtab[row*WSTR + m0] = e0 * inv;
            g_wtab[row*WSTR + m1] = e1 * inv;   // zero in pad region
        }
    }
}

// =====================================================================
// Kernel B: sequential scan; grid (B, 2 d-halves) x 512 threads.
// ALL w/e/a rows for this block staged into smem up front; the 200-step
// loop then reads only smem. 154KB dynamic smem -> 1 block/SM.
// =====================================================================
extern "C" __global__ void __launch_bounds__(512)
kB_scan(const int* __restrict__ skills, const int* __restrict__ responses,
        const float* __restrict__ Mv0)
{
    extern __shared__ float sb[];
    float* s_w = sb;               // L*64
    float* s_e = sb + L_*64;       // L*64 (this block's 64-d slice)
    float* s_a = sb + 2*L_*64;     // L*64
    __shared__ int s_x[L_], s_sk[L_];

    const int b   = blockIdx.x;
    const int tid = threadIdx.x;
    const int dhalf = blockIdx.y;        // 0 or 1

    for (int t = tid; t < L_; t += 512) {
        int sk = skills[b*L_ + t];
        int r  = responses[b*L_ + t];
        int mr = (r > -1) ? r : 0;
        s_sk[t] = sk;
        s_x[t]  = sk + NS_ * mr;
    }
    __syncthreads();

    {   // bulk stage: 16 float4 per t per table
        float4* sw4 = (float4*)s_w;
        float4* se4 = (float4*)s_e;
        float4* sa4 = (float4*)s_a;
        const float4* wt4 = (const float4*)g_wtab;
        const float4* et4 = (const float4*)g_etab;
        const float4* at4 = (const float4*)g_atab;
        const int dbase4 = dhalf * 16;   // d offset in float4 units
        for (int u = tid; u < L_*16; u += 512) {
            int t = u >> 4, c = u & 15;
            int xx = s_x[t], kk = s_sk[t];
            sw4[u] = __ldg(&wt4[kk*16 + c]);
            se4[u] = __ldg(&et4[(size_t)xx*32 + dbase4 + c]);
            sa4[u] = __ldg(&at4[(size_t)xx*32 + dbase4 + c]);
        }
    }
    __syncthreads();

    const int mg  = tid & 7;
    const int dl  = tid >> 3;
    const int d   = dhalf * 64 + dl;
    const int mbase = mg * 8;

    float mv[8];
    #pragma unroll
    for (int i = 0; i < 8; i++) {
        int m = mbase + i;
        mv[i] = (m < M_) ? Mv0[m*D_ + d] : 0.f;
    }

    float* rp = g_read + (size_t)b*L_*D_ + d;

    #pragma unroll 2
    for (int t = 0; t < L_; t++) {
        float ev = s_e[t*64 + dl];
        float av = s_a[t*64 + dl];
        float4 wa = *(const float4*)&s_w[t*64 + mbase];
        float4 wb = *(const float4*)&s_w[t*64 + mbase + 4];

        float rda = 0.f, rdb = 0.f;
        {
            float wv[4] = {wa.x, wa.y, wa.z, wa.w};
            #pragma unroll
            for (int s = 0; s < 4; s++) {
                float w = wv[s];
                rda = fmaf(w, mv[s], rda);          // read uses PRE-update Mv
                float g = fmaf(-ev, mv[s], av);     // a - e*mv
                mv[s] = fmaf(w, g, mv[s]);          // mv += w*(a - e*mv)
            }
        }
        {
            float wv[4] = {wb.x, wb.y, wb.z, wb.w};
            #pragma unroll
            for (int s = 0; s < 4; s++) {
                float w = wv[s];
                rdb = fmaf(w, mv[4+s], rdb);
                float g = fmaf(-ev, mv[4+s], av);
                mv[4+s] = fmaf(w, g, mv[4+s]);
            }
        }
        float rd = rda + rdb;
        rd += __shfl_xor_sync(0xffffffffu, rd, 1);
        rd += __shfl_xor_sync(0xffffffffu, rd, 2);
        rd += __shfl_xor_sync(0xffffffffu, rd, 4);
        if (mg == 0) rp[t*D_] = rd;
    }
}

// =====================================================================
// Kernel C: f = tanh(read @ f_Wr^T + kf_tab[skill] + f_b); p = sigmoid(f.p_W+p_b)
// 100 blocks x 1024 threads, 128 rows/block; 128KB smem -> 1 block/SM,
// 32 warps. Weight staging halved vs R7.
// =====================================================================
extern "C" __global__ void __launch_bounds__(1024, 1)
kC_out(const int* __restrict__ skills,
       const float* __restrict__ f_b,
       const float* __restrict__ p_W, const float* __restrict__ p_b,
       float* __restrict__ out)
{
    extern __shared__ float sm[];
    float* hx  = sm;                 // 128*128 read tile (64KB)
    float* fWT = sm + 128*D_;        // 128*128 transposed weights (64KB)
    __shared__ int s_sk[128];

    const int tid  = threadIdx.x;
    const int row0 = blockIdx.x * 128;

    if (tid < 128) s_sk[tid] = skills[row0 + tid];
    {
        float4* w4 = (float4*)fWT;
        const float4* WT4 = (const float4*)g_frT;
        #pragma unroll
        for (int i = 0; i < 4; i++) w4[tid + i*1024] = __ldg(&WT4[tid + i*1024]);
    }
    {
        float4* h4 = (float4*)hx;
        const float4* rd4 = (const float4*)g_read;
        #pragma unroll
        for (int i = 0; i < 4; i++) h4[tid + i*1024] = __ldg(&rd4[(size_t)row0*32 + tid + i*1024]);
    }
    __syncthreads();

    const int tx = tid & 31, ty = tid >> 5;   // ty 0..31
    const int r0 = ty * 4, c0 = tx * 4;

    float acc[4][4] = {};
    const float4* h4 = (const float4*)hx;
    #pragma unroll 4
    for (int k4 = 0; k4 < 32; k4++) {
        float4 hr[4];
        #pragma unroll
        for (int i = 0; i < 4; i++) hr[i] = h4[(r0+i)*32 + k4];
        #pragma unroll
        for (int s = 0; s < 4; s++) {
            int k = k4*4 + s;
            float4 w = *(const float4*)&fWT[k*D_ + c0];
            #pragma unroll
            for (int i = 0; i < 4; i++) {
                float hv = ((const float*)&hr[i])[s];
                acc[i][0] = fmaf(hv, w.x, acc[i][0]);
                acc[i][1] = fmaf(hv, w.y, acc[i][1]);
                acc[i][2] = fmaf(hv, w.z, acc[i][2]);
                acc[i][3] = fmaf(hv, w.w, acc[i][3]);
            }
        }
    }
    float4 fb = *(const float4*)&f_b[c0];
    float4 pw = *(const float4*)&p_W[c0];
    float pb = p_b[0];
    #pragma unroll
    for (int i = 0; i < 4; i++) {
        int row = row0 + r0 + i;
        int sk = s_sk[r0 + i];
        float4 kf = *(const float4*)&g_kftab[(size_t)sk*D_ + c0];
        float f0 = ftanh(acc[i][0] + kf.x + fb.x);
        float f1 = ftanh(acc[i][1] + kf.y + fb.y);
        float f2 = ftanh(acc[i][2] + kf.z + fb.z);
        float f3 = ftanh(acc[i][3] + kf.w + fb.w);
        float pp = f0*pw.x + f1*pw.y + f2*pw.z + f3*pw.w;
        #pragma unroll
        for (int o = 16; o >= 1; o >>= 1) pp += __shfl_xor_sync(0xffffffffu, pp, o);
        if (tx == 0) {
            int bb = row / L_, t = row % L_;
            if (t >= 1) out[bb*(L_-1) + (t-1)] = fsigmoid(pp + pb);
        }
    }
}

// =====================================================================
extern "C" void kernel_launch(void* const* d_in, const int* in_sizes, int n_in,
                              void* d_out, int out_size)
{
    const int*   skills    = (const int*)  d_in[0];
    const int*   responses = (const int*)  d_in[1];
    const float* k_emb     = (const float*)d_in[2];
    const float* v_emb     = (const float*)d_in[3];
    const float* Mk        = (const float*)d_in[4];
    const float* Mv0       = (const float*)d_in[5];
    const float* e_W       = (const float*)d_in[6];
    const float* e_b       = (const float*)d_in[7];
    const float* a_W       = (const float*)d_in[8];
    const float* a_b       = (const float*)d_in[9];
    const float* f_W       = (const float*)d_in[10];
    const float* f_b       = (const float*)d_in[11];
    const float* p_W       = (const float*)d_in[12];
    const float* p_b       = (const float*)d_in[13];
    float* out = (float*)d_out;

    const size_t SZA = (size_t)(64*D_ + D_*D_) * sizeof(float);    //  98304
    const size_t SZB = (size_t)(3*L_*64) * sizeof(float);          // 153600
    const size_t SZC = (size_t)(128*D_ + D_*D_) * sizeof(float);   // 131072

    cudaFuncSetAttribute(kA_tables, cudaFuncAttributeMaxDynamicSharedMemorySize, (int)SZA);
    cudaFuncSetAttribute(kB_scan,   cudaFuncAttributeMaxDynamicSharedMemorySize, (int)SZB);
    cudaFuncSetAttribute(kC_out,    cudaFuncAttributeMaxDynamicSharedMemorySize, (int)SZC);

    k0_transpose<<<dim3(16, 4), 256>>>(e_W, a_W, f_W);
    kA_tables<<<96, 512, SZA>>>(k_emb, v_emb, Mk, e_b, a_b);
    kB_scan<<<dim3(B_, 2), 512, SZB>>>(skills, responses, Mv0);
    kC_out<<<BL_/128, 1024, SZC>>>(skills, f_b, p_W, p_b, out);
}

// round 9
// speedup vs baseline: 2.2786x; 1.0791x over previous
#include <cuda_runtime.h>

#define B_  64
#define L_  200
#define NS_ 1000
#define D_  128
#define M_  50
#define BL_ (B_*L_)
#define WSTR 64   // padded w-row stride (slots 50..63 zero)

// -------- scratch (device globals; no allocation allowed) --------
__device__ float g_eWT[D_*D_];        // e_W transposed [k][d]
__device__ float g_aWT[D_*D_];        // a_W transposed
__device__ float g_frT[D_*D_];        // read-half of f_W transposed [k][d]
__device__ float g_fkT[D_*D_];        // k-half of f_W transposed
__device__ float g_wtab[1024*WSTR];   // softmax weights per skill (padded)
__device__ float g_etab[2048*D_];     // sigmoid erase per x (rows>=2000 junk)
__device__ float g_atab[2048*D_];     // tanh add per x
__device__ float g_kftab[1024*D_];    // k_emb[s] @ f_Wk^T (no bias/act)
__device__ float g_read[BL_*D_];      // read vectors

__device__ __forceinline__ float fsigmoid(float x){ return 1.f/(1.f+__expf(-x)); }
__device__ __forceinline__ float ftanh(float x){ float y; asm("tanh.approx.f32 %0, %1;":"=f"(y):"f"(x)); return y; }

// =====================================================================
// Kernel 0: transpose the 4 weight matrices once (tiled, conflict-free).
// =====================================================================
extern "C" __global__ void __launch_bounds__(256)
k0_transpose(const float* __restrict__ e_W, const float* __restrict__ a_W,
             const float* __restrict__ f_W)
{
    __shared__ float tile[32][33];
    const int m  = blockIdx.y;
    const int tb = blockIdx.x;
    const int d0 = (tb & 3) * 32;
    const int k0 = (tb >> 2) * 32;
    const int c  = threadIdx.x & 31;
    const int rb = threadIdx.x >> 5;

    const float* src; int stride, off; float* dst;
    if      (m == 0) { src = e_W; stride = D_;   off = 0;   dst = g_eWT; }
    else if (m == 1) { src = a_W; stride = D_;   off = 0;   dst = g_aWT; }
    else if (m == 2) { src = f_W; stride = 2*D_; off = 0;   dst = g_frT; }
    else             { src = f_W; stride = 2*D_; off = D_;  dst = g_fkT; }

    #pragma unroll
    for (int p = 0; p < 4; p++) {
        int r = rb + p*8;
        tile[r][c] = src[(size_t)(d0 + r)*stride + off + k0 + c];
    }
    __syncthreads();
    #pragma unroll
    for (int p = 0; p < 4; p++) {
        int r = rb + p*8;
        dst[(size_t)(k0 + r)*D_ + d0 + c] = tile[c][r];
    }
}

// =====================================================================
// Kernel A: build all tables. 56 blocks x 512 threads.
//   [0,16)  e-table  : 128 rows/block (2048 rows), 8x4 register tile
//   [16,32) a-table  : 128 rows/block
//   [32,40) kf-table : 128 rows/block (1024 rows)
//   [40,56) w-table  : 64 rows/block softmax (unchanged 4-row logic)
// smem: 64KB activations (max) + 64KB weights = 128KB -> 1 block/SM.
// =====================================================================
extern "C" __global__ void __launch_bounds__(512)
kA_tables(const float* __restrict__ k_emb, const float* __restrict__ v_emb,
          const float* __restrict__ Mk,
          const float* __restrict__ e_b, const float* __restrict__ a_b)
{
    extern __shared__ float sm[];
    float* sx = sm;                 // up to 128*128 activation tile (64KB)
    float* sw = sm + 128*D_;        // 128*128 transposed weights (64KB)
    const int tid = threadIdx.x;
    const int tx = tid & 31, ty = tid >> 5;   // ty 0..15
    const int c0 = tx * 4;
    const int bid = blockIdx.x;

    if (bid < 40) {
        // ------- e/a/kf tables: 128-row GEMM, 8x4 tile -------
        const int type  = (bid < 16) ? 0 : (bid < 32) ? 1 : 2;
        const int rbase = (type == 0 ? bid : type == 1 ? bid - 16 : bid - 32) * 128;
        const float* WT = (type == 0) ? g_eWT : (type == 1) ? g_aWT : g_fkT;
        const float* xs = (type == 2) ? k_emb : v_emb;
        const int rmax  = (type == 2) ? NS_ - 1 : 2*NS_ - 1;
        const int r0 = ty * 8;

        {   // stage transposed weights (4096 f4)
            float4* sw4 = (float4*)sw;
            const float4* WT4 = (const float4*)WT;
            #pragma unroll
            for (int i = 0; i < 8; i++) sw4[tid + i*512] = __ldg(&WT4[tid + i*512]);
        }
        {   // gather 128 activation rows (4096 f4)
            float4* s4 = (float4*)sx;
            const float4* xs4 = (const float4*)xs;
            #pragma unroll
            for (int i = 0; i < 8; i++) {
                int u = tid + i*512;
                int r = u >> 5, cc = u & 31;
                int rr = min(rbase + r, rmax);
                s4[u] = __ldg(&xs4[(size_t)rr*32 + cc]);
            }
        }
        __syncthreads();

        float acc[8][4] = {};
        const float4* s4 = (const float4*)sx;
        #pragma unroll 2
        for (int k4 = 0; k4 < 32; k4++) {
            float4 vr[8];
            #pragma unroll
            for (int i = 0; i < 8; i++) vr[i] = s4[(r0+i)*32 + k4];
            #pragma unroll
            for (int s = 0; s < 4; s++) {
                int k = 4*k4 + s;
                float4 w = *(const float4*)&sw[k*D_ + c0];
                #pragma unroll
                for (int i = 0; i < 8; i++) {
                    float vv = ((const float*)&vr[i])[s];
                    acc[i][0] = fmaf(vv, w.x, acc[i][0]);
                    acc[i][1] = fmaf(vv, w.y, acc[i][1]);
                    acc[i][2] = fmaf(vv, w.z, acc[i][2]);
                    acc[i][3] = fmaf(vv, w.w, acc[i][3]);
                }
            }
        }
        #pragma unroll
        for (int i = 0; i < 8; i++) {
            int row = rbase + r0 + i;
            float4 o;
            if (type == 0) {
                float4 bb = *(const float4*)&e_b[c0];
                o.x = fsigmoid(acc[i][0] + bb.x); o.y = fsigmoid(acc[i][1] + bb.y);
                o.z = fsigmoid(acc[i][2] + bb.z); o.w = fsigmoid(acc[i][3] + bb.w);
                *(float4*)&g_etab[(size_t)row*D_ + c0] = o;
            } else if (type == 1) {
                float4 bb = *(const float4*)&a_b[c0];
                o.x = ftanh(acc[i][0] + bb.x); o.y = ftanh(acc[i][1] + bb.y);
                o.z = ftanh(acc[i][2] + bb.z); o.w = ftanh(acc[i][3] + bb.w);
                *(float4*)&g_atab[(size_t)row*D_ + c0] = o;
            } else {
                o.x = acc[i][0]; o.y = acc[i][1]; o.z = acc[i][2]; o.w = acc[i][3];
                *(float4*)&g_kftab[(size_t)row*D_ + c0] = o;
            }
        }
    } else {
        // ---------------- w (softmax) table, 64 rows ----------------
        const int rbase = (bid - 40) * 64;
        const int r0 = ty * 4;
        float* MkT = sw;                      // 128*65 (pad 65: conflict-free)
        for (int i = tid; i < M_*D_; i += 512) {
            int m = i >> 7, k = i & 127;
            MkT[k*65 + m] = Mk[i];
        }
        for (int i = tid; i < D_*14; i += 512) {
            int k = i / 14, m = 50 + (i % 14);
            MkT[k*65 + m] = 0.f;
        }
        {
            float4* s4 = (float4*)sx;
            const float4* ke4 = (const float4*)k_emb;
            #pragma unroll
            for (int i = 0; i < 4; i++) {
                int u = tid + i*512;
                int r = u >> 5, cc = u & 31;
                int rr = min(rbase + r, NS_ - 1);
                s4[u] = __ldg(&ke4[(size_t)rr*32 + cc]);
            }
        }
        __syncthreads();

        const int m0 = tx, m1 = tx + 32;
        float a0[4] = {}, a1[4] = {};
        const float4* s4 = (const float4*)sx;
        #pragma unroll 4
        for (int k4 = 0; k4 < 32; k4++) {
            float4 kr[4];
            #pragma unroll
            for (int i = 0; i < 4; i++) kr[i] = s4[(r0+i)*32 + k4];
            #pragma unroll
            for (int s = 0; s < 4; s++) {
                int k = 4*k4 + s;
                float mv0 = MkT[k*65 + m0];
                float mv1 = MkT[k*65 + m1];
                #pragma unroll
                for (int i = 0; i < 4; i++) {
                    float kv = ((const float*)&kr[i])[s];
                    a0[i] = fmaf(kv, mv0, a0[i]);
                    a1[i] = fmaf(kv, mv1, a1[i]);
                }
            }
        }
        #pragma unroll
        for (int i = 0; i < 4; i++) {
            float v0 = a0[i];
            float v1 = (m1 < M_) ? a1[i] : -1e30f;
            float mx = fmaxf(v0, v1);
            #pragma unroll
            for (int o = 16; o >= 1; o >>= 1) mx = fmaxf(mx, __shfl_xor_sync(0xffffffffu, mx, o));
            float e0 = __expf(v0 - mx);
            float e1 = (m1 < M_) ? __expf(v1 - mx) : 0.f;
            float s = e0 + e1;
            #pragma unroll
            for (int o = 16; o >= 1; o >>= 1) s += __shfl_xor_sync(0xffffffffu, s, o);
            float inv = __frcp_rn(s);
            int row = rbase + r0 + i;
            g_wtab[row*WSTR + m0] = e0 * inv;
            g_wtab[row*WSTR + m1] = e1 * inv;   // zero in pad region
        }
    }
}

// =====================================================================
// Kernel B: sequential scan; grid (B, 2 d-halves) x 512 threads.
// Strided m-ownership: thread mg owns m in {mg, mg+8, .., mg+48} (7 slots,
// 56 total; m>=50 has w==0 -> exact no-op). FMA/iter 21 (was 24).
// All w/e/a staged to smem up front; 154KB -> 1 block/SM.
// =====================================================================
extern "C" __global__ void __launch_bounds__(512)
kB_scan(const int* __restrict__ skills, const int* __restrict__ responses,
        const float* __restrict__ Mv0)
{
    extern __shared__ float sb[];
    float* s_w = sb;               // L*64
    float* s_e = sb + L_*64;       // L*64 (this block's 64-d slice)
    float* s_a = sb + 2*L_*64;     // L*64
    __shared__ int s_x[L_], s_sk[L_];

    const int b   = blockIdx.x;
    const int tid = threadIdx.x;
    const int dhalf = blockIdx.y;        // 0 or 1

    for (int t = tid; t < L_; t += 512) {
        int sk = skills[b*L_ + t];
        int r  = responses[b*L_ + t];
        int mr = (r > -1) ? r : 0;
        s_sk[t] = sk;
        s_x[t]  = sk + NS_ * mr;
    }
    __syncthreads();

    {   // bulk stage: 16 float4 per t per table
        float4* sw4 = (float4*)s_w;
        float4* se4 = (float4*)s_e;
        float4* sa4 = (float4*)s_a;
        const float4* wt4 = (const float4*)g_wtab;
        const float4* et4 = (const float4*)g_etab;
        const float4* at4 = (const float4*)g_atab;
        const int dbase4 = dhalf * 16;
        for (int u = tid; u < L_*16; u += 512) {
            int t = u >> 4, c = u & 15;
            int xx = s_x[t], kk = s_sk[t];
            sw4[u] = __ldg(&wt4[kk*16 + c]);
            se4[u] = __ldg(&et4[(size_t)xx*32 + dbase4 + c]);
            sa4[u] = __ldg(&at4[(size_t)xx*32 + dbase4 + c]);
        }
    }
    __syncthreads();

    const int mg  = tid & 7;
    const int dl  = tid >> 3;
    const int d   = dhalf * 64 + dl;

    float mv[7];
    #pragma unroll
    for (int j = 0; j < 7; j++) {
        int m = mg + 8*j;
        mv[j] = (m < M_) ? Mv0[m*D_ + d] : 0.f;
    }

    float* rp = g_read + (size_t)b*L_*D_ + d;

    #pragma unroll 2
    for (int t = 0; t < L_; t++) {
        float ev = s_e[t*64 + dl];
        float av = s_a[t*64 + dl];
        const float* wrow = &s_w[t*64 + mg];

        float rda = 0.f, rdb = 0.f;
        #pragma unroll
        for (int j = 0; j < 7; j++) {
            float w = wrow[8*j];                 // broadcast-friendly scalar LDS
            float r_ = fmaf(w, mv[j], 0.f);
            if (j & 1) rdb += r_; else rda += r_;
            float g = fmaf(-ev, mv[j], av);      // a - e*mv
            mv[j] = fmaf(w, g, mv[j]);           // mv += w*(a - e*mv)
        }
        float rd = rda + rdb;
        rd += __shfl_xor_sync(0xffffffffu, rd, 1);
        rd += __shfl_xor_sync(0xffffffffu, rd, 2);
        rd += __shfl_xor_sync(0xffffffffu, rd, 4);
        if (mg == 0) rp[t*D_] = rd;
    }
}

// =====================================================================
// Kernel C: f = tanh(read @ f_Wr^T + kf_tab[skill] + f_b); p = sigmoid(f.p_W+p_b)
// 128 blocks x 640 threads, 100 rows/block (5x4 tile, ty 0..19).
// smem 114KB -> 1 block/SM; one clean 128-block wave (matches kB shape).
// =====================================================================
extern "C" __global__ void __launch_bounds__(640)
kC_out(const int* __restrict__ skills,
       const float* __restrict__ f_b,
       const float* __restrict__ p_W, const float* __restrict__ p_b,
       float* __restrict__ out)
{
    extern __shared__ float sm[];
    float* hx  = sm;                 // 100*128 read tile (50KB)
    float* fWT = sm + 100*D_;        // 128*128 transposed weights (64KB)
    __shared__ int s_sk[100];

    const int tid  = threadIdx.x;
    const int row0 = blockIdx.x * 100;

    if (tid < 100) s_sk[tid] = skills[row0 + tid];
    {
        float4* w4 = (float4*)fWT;
        const float4* WT4 = (const float4*)g_frT;
        for (int u = tid; u < 4096; u += 640) w4[u] = __ldg(&WT4[u]);
    }
    {
        float4* h4 = (float4*)hx;
        const float4* rd4 = (const float4*)g_read;
        for (int u = tid; u < 100*32; u += 640) h4[u] = __ldg(&rd4[(size_t)row0*32 + u]);
    }
    __syncthreads();

    const int tx = tid & 31, ty = tid >> 5;   // ty 0..19
    const int r0 = ty * 5, c0 = tx * 4;

    float acc[5][4] = {};
    const float4* h4 = (const float4*)hx;
    #pragma unroll 2
    for (int k4 = 0; k4 < 32; k4++) {
        float4 hr[5];
        #pragma unroll
        for (int i = 0; i < 5; i++) hr[i] = h4[(r0+i)*32 + k4];
        #pragma unroll
        for (int s = 0; s < 4; s++) {
            int k = k4*4 + s;
            float4 w = *(const float4*)&fWT[k*D_ + c0];
            #pragma unroll
            for (int i = 0; i < 5; i++) {
                float hv = ((const float*)&hr[i])[s];
                acc[i][0] = fmaf(hv, w.x, acc[i][0]);
                acc[i][1] = fmaf(hv, w.y, acc[i][1]);
                acc[i][2] = fmaf(hv, w.z, acc[i][2]);
                acc[i][3] = fmaf(hv, w.w, acc[i][3]);
            }
        }
    }
    float4 fb = *(const float4*)&f_b[c0];
    float4 pw = *(const float4*)&p_W[c0];
    float pb = p_b[0];
    #pragma unroll
    for (int i = 0; i < 5; i++) {
        int row = row0 + r0 + i;
        int sk = s_sk[r0 + i];
        float4 kf = *(const float4*)&g_kftab[(size_t)sk*D_ + c0];
        float f0 = ftanh(acc[i][0] + kf.x + fb.x);
        float f1 = ftanh(acc[i][1] + kf.y + fb.y);
        float f2 = ftanh(acc[i][2] + kf.z + fb.z);
        float f3 = ftanh(acc[i][3] + kf.w + fb.w);
        float pp = f0*pw.x + f1*pw.y + f2*pw.z + f3*pw.w;
        #pragma unroll
        for (int o = 16; o >= 1; o >>= 1) pp += __shfl_xor_sync(0xffffffffu, pp, o);
        if (tx == 0) {
            int bb = row / L_, t = row % L_;
            if (t >= 1) out[bb*(L_-1) + (t-1)] = fsigmoid(pp + pb);
        }
    }
}

// =====================================================================
extern "C" void kernel_launch(void* const* d_in, const int* in_sizes, int n_in,
                              void* d_out, int out_size)
{
    const int*   skills    = (const int*)  d_in[0];
    const int*   responses = (const int*)  d_in[1];
    const float* k_emb     = (const float*)d_in[2];
    const float* v_emb     = (const float*)d_in[3];
    const float* Mk        = (const float*)d_in[4];
    const float* Mv0       = (const float*)d_in[5];
    const float* e_W       = (const float*)d_in[6];
    const float* e_b       = (const float*)d_in[7];
    const float* a_W       = (const float*)d_in[8];
    const float* a_b       = (const float*)d_in[9];
    const float* f_W       = (const float*)d_in[10];
    const float* f_b       = (const float*)d_in[11];
    const float* p_W       = (const float*)d_in[12];
    const float* p_b       = (const float*)d_in[13];
    float* out = (float*)d_out;

    const size_t SZA = (size_t)(128*D_ + D_*D_) * sizeof(float);   // 131072
    const size_t SZB = (size_t)(3*L_*64) * sizeof(float);          // 153600
    const size_t SZC = (size_t)(100*D_ + D_*D_) * sizeof(float);   // 116736

    cudaFuncSetAttribute(kA_tables, cudaFuncAttributeMaxDynamicSharedMemorySize, (int)SZA);
    cudaFuncSetAttribute(kB_scan,   cudaFuncAttributeMaxDynamicSharedMemorySize, (int)SZB);
    cudaFuncSetAttribute(kC_out,    cudaFuncAttributeMaxDynamicSharedMemorySize, (int)SZC);

    k0_transpose<<<dim3(16, 4), 256>>>(e_W, a_W, f_W);
    kA_tables<<<56, 512, SZA>>>(k_emb, v_emb, Mk, e_b, a_b);
    kB_scan<<<dim3(B_, 2), 512, SZB>>>(skills, responses, Mv0);
    kC_out<<<128, 640, SZC>>>(skills, f_b, p_W, p_b, out);
}